// round 4
// baseline (speedup 1.0000x reference)
#include <cuda_runtime.h>
#include <cstdint>

#define MAXN 50000
#define D 64
#define TP 68  // padded smem row (floats); 272 B, multiple of 16

// Scratch (device globals; float4 type => structural 16B alignment)
__device__ float4 g_agg4[MAXN * (D / 4)];
__device__ float  g_deg[MAXN];

// ---------------------------------------------------------------------------
// Kernel 1: zero scratch
// ---------------------------------------------------------------------------
__global__ void zero_kernel(int n_nodes) {
    int i = blockIdx.x * blockDim.x + threadIdx.x;
    int n4 = n_nodes * (D / 4);
    if (i < n4) g_agg4[i] = make_float4(0.f, 0.f, 0.f, 0.f);
    if (i < n_nodes) g_deg[i] = 0.f;
}

// ---------------------------------------------------------------------------
// Kernel 2 (fat): blocks [0,nG) = self-GEMM (independent of scatter, placed
// first so they fill wave 1 and overlap); blocks [nG,..) = edge scatter.
//   self:    out[n][o] = sum_k x[n][k]*Ws[o][k] + (bs[o]+bn[o])
//   scatter: agg[row] += x[col] (RED.128, 16 lanes/edge); deg[row] += 1
// ---------------------------------------------------------------------------
__global__ __launch_bounds__(256, 5) void fused_scatter_selfgemm(
    const float* __restrict__ x, const int* __restrict__ ei,
    const float* __restrict__ Ws, const float* __restrict__ bs,
    const float* __restrict__ bn,
    float* __restrict__ out, int N, int E, int nG)
{
    const int tid = threadIdx.x;

    if (blockIdx.x >= nG) {
        // ----- scatter branch -----
        long long gid = (long long)(blockIdx.x - nG) * 256 + tid;
        int edge = (int)(gid >> 4);
        int lane = (int)(gid & 15);
        if (edge >= E) return;

        int r = min(max(ei[edge], 0), N - 1);      // destination
        int c = min(max(ei[E + edge], 0), N - 1);  // source

        float4 v = __ldg(reinterpret_cast<const float4*>(x) + (size_t)c * (D / 4) + lane);
        float4* dst = g_agg4 + (size_t)r * (D / 4) + lane;
        asm volatile("red.global.add.v4.f32 [%0], {%1, %2, %3, %4};"
                     :: "l"(dst), "f"(v.x), "f"(v.y), "f"(v.z), "f"(v.w)
                     : "memory");
        if (lane == 0) atomicAdd(g_deg + r, 1.0f);
        return;
    }

    // ----- self-GEMM branch: 64-node x 64-out tile, 4x4 register tile -----
    extern __shared__ float sh[];
    float* Wts  = sh;               // [64][TP] transposed weights
    float* xt   = sh + 64 * TP;     // [64][TP] transposed x tile
    float* bias = sh + 2 * 64 * TP; // [64]

    for (int i = tid; i < 64 * 64; i += 256) {
        int o = i >> 6, k = i & 63;
        Wts[k * TP + o] = Ws[i];
    }
    if (tid < 64) bias[tid] = bs[tid] + bn[tid];

    const int node0 = blockIdx.x << 6;
    for (int i = tid; i < 64 * 64; i += 256) {
        int n = i >> 6, k = i & 63;
        int node = node0 + n;
        xt[k * TP + n] = (node < N) ? x[(size_t)node * D + k] : 0.f;
    }
    __syncthreads();

    const int to = tid & 15;   // 4 outs:  4*to..
    const int tn = tid >> 4;   // 4 nodes: 4*tn..

    float acc[4][4];
    #pragma unroll
    for (int i = 0; i < 4; i++)
        #pragma unroll
        for (int j = 0; j < 4; j++) acc[i][j] = 0.f;

    #pragma unroll
    for (int k = 0; k < 64; k++) {
        float4 a = *reinterpret_cast<const float4*>(&xt[k * TP + 4 * tn]);
        float4 w = *reinterpret_cast<const float4*>(&Wts[k * TP + 4 * to]);
        float av[4] = {a.x, a.y, a.z, a.w};
        float wv[4] = {w.x, w.y, w.z, w.w};
        #pragma unroll
        for (int i = 0; i < 4; i++)
            #pragma unroll
            for (int j = 0; j < 4; j++) acc[i][j] += av[i] * wv[j];
    }

    float bj[4];
    #pragma unroll
    for (int j = 0; j < 4; j++) bj[j] = bias[4 * to + j];

    #pragma unroll
    for (int i = 0; i < 4; i++) {
        int node = node0 + 4 * tn + i;
        if (node < N) {
            float4 r;
            r.x = acc[i][0] + bj[0];
            r.y = acc[i][1] + bj[1];
            r.z = acc[i][2] + bj[2];
            r.w = acc[i][3] + bj[3];
            *reinterpret_cast<float4*>(&out[(size_t)node * D + 4 * to]) = r;
        }
    }
}

// ---------------------------------------------------------------------------
// Kernel 3: neighbor GEMM + degree normalize, accumulate into out.
//   out[n][o] += (sum_k agg[n][k]*Wn[o][k]) / max(deg[n],1)
// ---------------------------------------------------------------------------
__global__ __launch_bounds__(256, 5) void neigh_gemm_kernel(
    const float* __restrict__ Wn, float* __restrict__ out, int N)
{
    extern __shared__ float sh[];
    float* Wtn = sh;             // [64][TP]
    float* at  = sh + 64 * TP;   // [64][TP] transposed agg tile

    const int tid = threadIdx.x;
    const float* agg = reinterpret_cast<const float*>(g_agg4);

    for (int i = tid; i < 64 * 64; i += 256) {
        int o = i >> 6, k = i & 63;
        Wtn[k * TP + o] = Wn[i];
    }

    const int node0 = blockIdx.x << 6;
    for (int i = tid; i < 64 * 64; i += 256) {
        int n = i >> 6, k = i & 63;
        int node = node0 + n;
        at[k * TP + n] = (node < N) ? agg[(size_t)node * D + k] : 0.f;
    }
    __syncthreads();

    const int to = tid & 15;
    const int tn = tid >> 4;

    float acc[4][4];
    #pragma unroll
    for (int i = 0; i < 4; i++)
        #pragma unroll
        for (int j = 0; j < 4; j++) acc[i][j] = 0.f;

    #pragma unroll
    for (int k = 0; k < 64; k++) {
        float4 a = *reinterpret_cast<const float4*>(&at[k * TP + 4 * tn]);
        float4 w = *reinterpret_cast<const float4*>(&Wtn[k * TP + 4 * to]);
        float av[4] = {a.x, a.y, a.z, a.w};
        float wv[4] = {w.x, w.y, w.z, w.w};
        #pragma unroll
        for (int i = 0; i < 4; i++)
            #pragma unroll
            for (int j = 0; j < 4; j++) acc[i][j] += av[i] * wv[j];
    }

    #pragma unroll
    for (int i = 0; i < 4; i++) {
        int node = node0 + 4 * tn + i;
        if (node < N) {
            float inv = 1.0f / fmaxf(g_deg[node], 1.0f);
            float4* p = reinterpret_cast<float4*>(&out[(size_t)node * D + 4 * to]);
            float4 cur = *p;
            cur.x += acc[i][0] * inv;
            cur.y += acc[i][1] * inv;
            cur.z += acc[i][2] * inv;
            cur.w += acc[i][3] * inv;
            *p = cur;
        }
    }
}

// ---------------------------------------------------------------------------
// Launch
// ---------------------------------------------------------------------------
extern "C" void kernel_launch(void* const* d_in, const int* in_sizes, int n_in,
                              void* d_out, int out_size) {
    const float* x  = (const float*)d_in[0];
    const int*   ei = (const int*)d_in[1];   // int64 reference -> int32 on device
    const float* Ws = (const float*)d_in[2];
    const float* bs = (const float*)d_in[3];
    const float* Wn = (const float*)d_in[4];
    const float* bn = (const float*)d_in[5];
    float*       out = (float*)d_out;

    const int N = in_sizes[0] / D;
    const int E = in_sizes[1] / 2;

    // 1) zero scratch
    {
        int threads = N * (D / 4);
        zero_kernel<<<(threads + 255) / 256, 256>>>(N);
    }
    // 2) fat kernel: self-GEMM blocks first (wave 1), then scatter blocks
    const int nG = (N + 63) / 64;
    {
        long long scatterThreads = (long long)E * 16;
        int scatterBlocks = (int)((scatterThreads + 255) / 256);
        int smem = (2 * 64 * TP + 64) * (int)sizeof(float);  // 35072 B
        fused_scatter_selfgemm<<<nG + scatterBlocks, 256, smem>>>(
            x, ei, Ws, bs, bn, out, N, E, nG);
    }
    // 3) neighbor GEMM + normalize, accumulate into out
    {
        int smem = (2 * 64 * TP) * (int)sizeof(float);  // 34816 B
        neigh_gemm_kernel<<<nG, 256, smem>>>(Wn, out, N);
    }
}